// round 10
// baseline (speedup 1.0000x reference)
#include <cuda_runtime.h>
#include <cstdint>

#define NN 100000
#define NE 1600000
#define DIM 128
#define SLOTS 128

typedef unsigned long long u64;

// ---------------------------------------------------------------------------
// Scratch (__device__ globals)
// ---------------------------------------------------------------------------
__device__ float g_mean[NN * DIM];
__device__ float g_h1[NN * DIM];
__device__ float g_h2[NN * DIM];
__device__ int   g_cursor[NN];
__device__ int   g_csrsrc[NN * SLOTS];

// ---------------------------------------------------------------------------
// f32x2 helpers (Blackwell packed fp32 FMA)
// ---------------------------------------------------------------------------
__device__ __forceinline__ u64 dup2(float v) {
    u64 r; asm("mov.b64 %0, {%1, %1};" : "=l"(r) : "f"(v)); return r;
}
__device__ __forceinline__ float2 unpack2(u64 v) {
    float2 p; asm("mov.b64 {%0, %1}, %2;" : "=f"(p.x), "=f"(p.y) : "l"(v)); return p;
}
__device__ __forceinline__ void ffma2(u64& d, u64 a, u64 b) {
    asm("fma.rn.f32x2 %0, %1, %2, %0;" : "+l"(d) : "l"(a), "l"(b));
}

// ---------------------------------------------------------------------------
// padded-bucket CSR build
// ---------------------------------------------------------------------------
__global__ void k_init_cursor() {
    int i = blockIdx.x * blockDim.x + threadIdx.x;
    if (i < NN) g_cursor[i] = i * SLOTS;
}

__global__ void k_bucket(const int* __restrict__ src, const int* __restrict__ dst) {
    int e = blockIdx.x * blockDim.x + threadIdx.x;
    if (e < NE) {
        int d = dst[e];
        int pos = atomicAdd(&g_cursor[d], 1);
        if (pos < d * SLOTS + SLOTS)
            g_csrsrc[pos] = src[e];
    }
}

// ---------------------------------------------------------------------------
// pull-mode mean aggregation: one warp per node, lane owns one float4.
// ---------------------------------------------------------------------------
__global__ void __launch_bounds__(256)
k_agg(const float* __restrict__ x, float* __restrict__ mean) {
    int node = (blockIdx.x * blockDim.x + threadIdx.x) >> 5;
    int lane = threadIdx.x & 31;
    if (node >= NN) return;
    int beg = node * SLOTS;
    int d   = min(__ldg(g_cursor + node) - beg, SLOTS);
    int end = beg + d;

    const float4* xv = (const float4*)x;
    float4 acc = make_float4(0.f, 0.f, 0.f, 0.f);
    for (int e = beg; e < end; e += 8) {
        int idx[8];
#pragma unroll
        for (int j = 0; j < 8; ++j)
            idx[j] = (e + j < end) ? __ldg(g_csrsrc + e + j) : -1;
#pragma unroll
        for (int j = 0; j < 8; ++j) {
            if (idx[j] >= 0) {
                float4 v = __ldg(xv + (size_t)idx[j] * 32 + lane);
                acc.x += v.x; acc.y += v.y; acc.z += v.z; acc.w += v.w;
            }
        }
    }
    float inv = (d > 0) ? (1.0f / (float)d) : 0.0f;
    acc.x *= inv; acc.y *= inv; acc.z *= inv; acc.w *= inv;
    ((float4*)(mean + (size_t)node * DIM))[lane] = acc;
}

// ---------------------------------------------------------------------------
// fused SAGE GEMM — R7 inner-loop economics at 2x occupancy:
//   out[n,:] = act( mean[n,:] @ Wl + hin[n,:] @ Wr + b )
//
// 512 threads = (tx 0..15: 8 cols) x (ty 0..31: rows {ty, ty+32}), block tile
// 64 rows x 128 cols, acc 2x4 u64/thread (16 regs). launch_bounds(512,2)
// forces <=64 regs -> 32 warps/SM (8/SMSP), double R7/R9's 16 — the exposed
// LDS/LDG latency that held issue at 26% gets covered by warp parallelism.
// Weights via LDG.128 pairs (ulonglong2): WS 128KB < L1D 160KB (228-2x34KB).
// Per warp per 4k: 2 LDS.128 (broadcast rows) + 8 LDG.128 + 32 FFMA2.
// ---------------------------------------------------------------------------
template <bool RELU>
__global__ void __launch_bounds__(512, 2)
k_gemm(const float* __restrict__ mean,
       const float* __restrict__ hin,
       const float* __restrict__ Wl,
       const float* __restrict__ Wr,
       const float* __restrict__ bias,
       float* __restrict__ out) {
    constexpr int ROWS = 64;
    constexpr int STR  = DIM + 4;   // 132 floats, rows 16B-aligned
    __shared__ float s_in[ROWS * STR];

    const int tx = threadIdx.x & 15;   // cols [tx*8, tx*8+8)
    const int ty = threadIdx.x >> 4;   // rows {ty, ty+32}
    const int row0 = blockIdx.x * ROWS;

    u64 acc[2][4];
#pragma unroll
    for (int i = 0; i < 2; ++i)
#pragma unroll
        for (int j = 0; j < 4; ++j) acc[i][j] = 0ull;

#pragma unroll
    for (int phase = 0; phase < 2; ++phase) {
        const float* base = phase ? hin : mean;
        const float* W    = phase ? Wr  : Wl;

        __syncthreads();
        // stage 64x128 input tile (2048 float4 over 512 threads)
        for (int t = threadIdx.x; t < ROWS * 32; t += 512) {
            int r  = t >> 5;
            int c4 = t & 31;
            int grow = row0 + r;
            float4 v = make_float4(0.f, 0.f, 0.f, 0.f);
            if (grow < NN)
                v = __ldg(((const float4*)(base + (size_t)grow * DIM)) + c4);
            *(float4*)(s_in + r * STR + c4 * 4) = v;
        }
        __syncthreads();

        const ulonglong2* Wp2 = (const ulonglong2*)W;  // [k*32 + c2]
#pragma unroll 4
        for (int k0 = 0; k0 < DIM; k0 += 4) {
            float4 sv0 = *(const float4*)(s_in + ty * STR + k0);
            float4 sv1 = *(const float4*)(s_in + (ty + 32) * STR + k0);
#pragma unroll
            for (int kk = 0; kk < 4; ++kk) {
                int k = k0 + kk;
                ulonglong2 wa = __ldg(Wp2 + k * 32 + tx * 2);
                ulonglong2 wb = __ldg(Wp2 + k * 32 + tx * 2 + 1);
                float f0 = (kk == 0) ? sv0.x : (kk == 1) ? sv0.y
                           : (kk == 2) ? sv0.z : sv0.w;
                float f1 = (kk == 0) ? sv1.x : (kk == 1) ? sv1.y
                           : (kk == 2) ? sv1.z : sv1.w;
                u64 s0 = dup2(f0);
                u64 s1 = dup2(f1);
                ffma2(acc[0][0], s0, wa.x);
                ffma2(acc[0][1], s0, wa.y);
                ffma2(acc[0][2], s0, wb.x);
                ffma2(acc[0][3], s0, wb.y);
                ffma2(acc[1][0], s1, wa.x);
                ffma2(acc[1][1], s1, wa.y);
                ffma2(acc[1][2], s1, wb.x);
                ffma2(acc[1][3], s1, wb.y);
            }
        }
    }

    // epilogue
    float4 b0 = __ldg((const float4*)(bias + tx * 8));
    float4 b1 = __ldg((const float4*)(bias + tx * 8) + 1);

#pragma unroll
    for (int i = 0; i < 2; ++i) {
        int grow = row0 + ty + i * 32;
        if (grow >= NN) continue;
        float2 p0 = unpack2(acc[i][0]);
        float2 p1 = unpack2(acc[i][1]);
        float2 p2 = unpack2(acc[i][2]);
        float2 p3 = unpack2(acc[i][3]);
        float4 o0 = make_float4(p0.x + b0.x, p0.y + b0.y, p1.x + b0.z, p1.y + b0.w);
        float4 o1 = make_float4(p2.x + b1.x, p2.y + b1.y, p3.x + b1.z, p3.y + b1.w);
        if (RELU) {
            o0.x = fmaxf(o0.x, 0.f); o0.y = fmaxf(o0.y, 0.f);
            o0.z = fmaxf(o0.z, 0.f); o0.w = fmaxf(o0.w, 0.f);
            o1.x = fmaxf(o1.x, 0.f); o1.y = fmaxf(o1.y, 0.f);
            o1.z = fmaxf(o1.z, 0.f); o1.w = fmaxf(o1.w, 0.f);
        }
        float* op = out + (size_t)grow * DIM + tx * 8;
        *(float4*)(op)     = o0;
        *(float4*)(op + 4) = o1;
    }
}

// ---------------------------------------------------------------------------
// kernel_launch — launch index 3 = k_gemm layer 1 (ncu target)
// inputs: t, x, edge_index, W1_l, W1_r, b1, W2_l, W2_r, b2, W3_l, W3_r, b3
// ---------------------------------------------------------------------------
extern "C" void kernel_launch(void* const* d_in, const int* in_sizes, int n_in,
                              void* d_out, int out_size) {
    const float* x   = (const float*)d_in[1];
    const int*   ei  = (const int*)d_in[2];
    const int*   src = ei;
    const int*   dst = ei + NE;
    const float* W1l = (const float*)d_in[3];
    const float* W1r = (const float*)d_in[4];
    const float* b1  = (const float*)d_in[5];
    const float* W2l = (const float*)d_in[6];
    const float* W2r = (const float*)d_in[7];
    const float* b2  = (const float*)d_in[8];
    const float* W3l = (const float*)d_in[9];
    const float* W3r = (const float*)d_in[10];
    const float* b3  = (const float*)d_in[11];
    float* out = (float*)d_out;

    float *mean, *h1, *h2;
    cudaGetSymbolAddress((void**)&mean, g_mean);
    cudaGetSymbolAddress((void**)&h1,  g_h1);
    cudaGetSymbolAddress((void**)&h2,  g_h2);

    const int AGG_BLOCKS  = (NN * 32 + 255) / 256;
    const int GEMM_BLOCKS = (NN + 63) / 64;

    // padded-bucket CSR build (launches 0-1)
    k_init_cursor<<<(NN + 255) / 256, 256>>>();
    k_bucket<<<(NE + 255) / 256, 256>>>(src, dst);

    // layer 1 (launch 2 = agg, launch 3 = gemm -> ncu target)
    k_agg<<<AGG_BLOCKS, 256>>>(x, mean);
    k_gemm<true><<<GEMM_BLOCKS, 512>>>(mean, x, W1l, W1r, b1, h1);

    // layer 2
    k_agg<<<AGG_BLOCKS, 256>>>(h1, mean);
    k_gemm<true><<<GEMM_BLOCKS, 512>>>(mean, h1, W2l, W2r, b2, h2);

    // layer 3 (no relu)
    k_agg<<<AGG_BLOCKS, 256>>>(h2, mean);
    k_gemm<false><<<GEMM_BLOCKS, 512>>>(mean, h2, W3l, W3r, b3, out);
}

// round 11
// speedup vs baseline: 2.4498x; 2.4498x over previous
#include <cuda_runtime.h>
#include <cuda_bf16.h>
#include <cstdint>

#define NN 100000
#define NE 1600000
#define DIM 128
#define SLOTS 128
#define MT 128                    // M tile per block
#define WSTR 136                  // padded bf16 row stride (272B: conflict-free ldmatrix)
#define GRID_MMA ((NN + MT - 1) / MT)   // 782

typedef unsigned long long u64;

// ---------------------------------------------------------------------------
// Scratch (__device__ globals)
// ---------------------------------------------------------------------------
__device__ float g_mean[NN * DIM];
__device__ float g_h1[NN * DIM];
__device__ float g_h2[NN * DIM];
__device__ int   g_cursor[NN];
__device__ int   g_csrsrc[NN * SLOTS];
// pre-split transposed weights: [matrix 0..5][hi=0/lo=1][n*WSTR + k]
__device__ __nv_bfloat16 g_wbf[6][2][DIM * WSTR];

// ---------------------------------------------------------------------------
// helpers
// ---------------------------------------------------------------------------
__device__ __forceinline__ uint32_t smem_u32(const void* p) {
    uint32_t a;
    asm("{ .reg .u64 t; cvta.to.shared.u64 t, %1; cvt.u32.u64 %0, t; }" : "=r"(a) : "l"(p));
    return a;
}

__device__ __forceinline__ void ldmatrix_x4(uint32_t* r, uint32_t addr) {
    asm volatile("ldmatrix.sync.aligned.m8n8.x4.shared.b16 {%0,%1,%2,%3}, [%4];"
                 : "=r"(r[0]), "=r"(r[1]), "=r"(r[2]), "=r"(r[3]) : "r"(addr));
}
__device__ __forceinline__ void ldmatrix_x2(uint32_t* r, uint32_t addr) {
    asm volatile("ldmatrix.sync.aligned.m8n8.x2.shared.b16 {%0,%1}, [%2];"
                 : "=r"(r[0]), "=r"(r[1]) : "r"(addr));
}
__device__ __forceinline__ void mma_bf16(float* d, const uint32_t* a, const uint32_t* b) {
    asm volatile(
        "mma.sync.aligned.m16n8k16.row.col.f32.bf16.bf16.f32 "
        "{%0,%1,%2,%3}, {%4,%5,%6,%7}, {%8,%9}, {%0,%1,%2,%3};"
        : "+f"(d[0]), "+f"(d[1]), "+f"(d[2]), "+f"(d[3])
        : "r"(a[0]), "r"(a[1]), "r"(a[2]), "r"(a[3]), "r"(b[0]), "r"(b[1]));
}

// ---------------------------------------------------------------------------
// prep: cursor init + 6 weight matrices -> transposed, split (hi/lo bf16)
// ---------------------------------------------------------------------------
#define NB_INIT ((NN + 255) / 256)

__global__ void k_prep(const float* W0, const float* W1, const float* W2,
                       const float* W3, const float* W4, const float* W5) {
    int b = blockIdx.x;
    if (b < NB_INIT) {
        int i = b * 256 + threadIdx.x;
        if (i < NN) g_cursor[i] = i * SLOTS;
        return;
    }
    int m = b - NB_INIT;
    const float* W = (m == 0) ? W0 : (m == 1) ? W1 : (m == 2) ? W2
                     : (m == 3) ? W3 : (m == 4) ? W4 : W5;
    __nv_bfloat16* wh = &g_wbf[m][0][0];
    __nv_bfloat16* wl = &g_wbf[m][1][0];
    for (int e = threadIdx.x; e < DIM * DIM; e += 256) {
        int n = e >> 7, k = e & 127;
        float v = __ldg(W + k * DIM + n);           // BT[n][k] = W[k][n]
        __nv_bfloat16 h = __float2bfloat16(v);
        __nv_bfloat16 l = __float2bfloat16(v - __bfloat162float(h));
        wh[n * WSTR + k] = h;
        wl[n * WSTR + k] = l;
    }
}

__global__ void k_bucket(const int* __restrict__ src, const int* __restrict__ dst) {
    int e = blockIdx.x * blockDim.x + threadIdx.x;
    if (e < NE) {
        int d = dst[e];
        int pos = atomicAdd(&g_cursor[d], 1);
        if (pos < d * SLOTS + SLOTS)
            g_csrsrc[pos] = src[e];
    }
}

// ---------------------------------------------------------------------------
// pull-mode mean aggregation (unchanged): one warp per node.
// ---------------------------------------------------------------------------
__global__ void __launch_bounds__(256)
k_agg(const float* __restrict__ x, float* __restrict__ mean) {
    int node = (blockIdx.x * blockDim.x + threadIdx.x) >> 5;
    int lane = threadIdx.x & 31;
    if (node >= NN) return;
    int beg = node * SLOTS;
    int d   = min(__ldg(g_cursor + node) - beg, SLOTS);
    int end = beg + d;

    const float4* xv = (const float4*)x;
    float4 acc = make_float4(0.f, 0.f, 0.f, 0.f);
    for (int e = beg; e < end; e += 8) {
        int idx[8];
#pragma unroll
        for (int j = 0; j < 8; ++j)
            idx[j] = (e + j < end) ? __ldg(g_csrsrc + e + j) : -1;
#pragma unroll
        for (int j = 0; j < 8; ++j) {
            if (idx[j] >= 0) {
                float4 v = __ldg(xv + (size_t)idx[j] * 32 + lane);
                acc.x += v.x; acc.y += v.y; acc.z += v.z; acc.w += v.w;
            }
        }
    }
    float inv = (d > 0) ? (1.0f / (float)d) : 0.0f;
    acc.x *= inv; acc.y *= inv; acc.z *= inv; acc.w *= inv;
    ((float4*)(mean + (size_t)node * DIM))[lane] = acc;
}

// ---------------------------------------------------------------------------
// tensor-core SAGE GEMM (mma.sync bf16, split-precision):
//   out = act( mean @ Wl + hin @ Wr + b ),  A@W ~ AhWh + AhWl + AlWh
//
// 256 threads = 8 warps; M-tile 128 (warp w owns rows w*16..w*16+15), N=128.
// SMEM (139264 B): Ah | Al | Bh | Bl, each 128 x WSTR bf16. Per phase: stage
// A (f32 -> hi/lo bf16) + copy pre-split weights, then 8 k-steps x 16 n-tiles
// x 3 MMAs with ldmatrix-loaded fragments. D: 64 f32 regs/thread, both phases
// accumulate; bias+ReLU epilogue from fragments.
// ---------------------------------------------------------------------------
template <bool RELU>
__global__ void __launch_bounds__(256)
k_mma(const float* __restrict__ mean, const float* __restrict__ hin,
      const __nv_bfloat16* __restrict__ wl_h, const __nv_bfloat16* __restrict__ wl_l,
      const __nv_bfloat16* __restrict__ wr_h, const __nv_bfloat16* __restrict__ wr_l,
      const float* __restrict__ bias, float* __restrict__ out) {
    extern __shared__ __nv_bfloat16 sm[];
    constexpr int TILE = DIM * WSTR;              // 17408 bf16 = 34816 B
    __nv_bfloat16* sAH = sm;
    __nv_bfloat16* sAL = sm + TILE;
    __nv_bfloat16* sBH = sm + 2 * TILE;
    __nv_bfloat16* sBL = sm + 3 * TILE;
    const uint32_t base = smem_u32(sm);
    const uint32_t AH = base, AL = base + TILE * 2,
                   BH = base + 4 * TILE, BL = base + 6 * TILE;

    const int tid  = threadIdx.x;
    const int wid  = tid >> 5;
    const int lane = tid & 31;
    const int row0 = blockIdx.x * MT;
    const int wrow = wid * 16;

    // ldmatrix lane offsets (bytes)
    const uint32_t aoff = ((wrow + ((lane >> 3) & 1) * 8 + (lane & 7)) * WSTR
                           + ((lane >> 4) * 8)) * 2;
    const int bl8  = lane & 7;
    const int bk8  = ((lane >> 3) & 1) * 8;   // lanes 0-15 matter for x2

    float d[16][4];
#pragma unroll
    for (int n = 0; n < 16; ++n)
#pragma unroll
        for (int j = 0; j < 4; ++j) d[n][j] = 0.f;

#pragma unroll
    for (int phase = 0; phase < 2; ++phase) {
        const float* A = phase ? hin : mean;
        const __nv_bfloat16* WH = phase ? wr_h : wl_h;
        const __nv_bfloat16* WL = phase ? wr_l : wl_l;

        __syncthreads();   // previous phase's smem reads complete
        // stage A: split f32 -> hi/lo bf16
        for (int t = tid; t < MT * 32; t += 256) {
            int r  = t >> 5;
            int c4 = (t & 31) * 4;
            int grow = row0 + r;
            float4 v = make_float4(0.f, 0.f, 0.f, 0.f);
            if (grow < NN)
                v = __ldg((const float4*)(A + (size_t)grow * DIM) + (t & 31));
            __nv_bfloat16 h0 = __float2bfloat16(v.x), h1 = __float2bfloat16(v.y),
                          h2 = __float2bfloat16(v.z), h3 = __float2bfloat16(v.w);
            __nv_bfloat16 l0 = __float2bfloat16(v.x - __bfloat162float(h0));
            __nv_bfloat16 l1 = __float2bfloat16(v.y - __bfloat162float(h1));
            __nv_bfloat16 l2 = __float2bfloat16(v.z - __bfloat162float(h2));
            __nv_bfloat16 l3 = __float2bfloat16(v.w - __bfloat162float(h3));
            uint2 hp, lp;
            hp.x = (uint32_t)__bfloat16_as_ushort(h0) | ((uint32_t)__bfloat16_as_ushort(h1) << 16);
            hp.y = (uint32_t)__bfloat16_as_ushort(h2) | ((uint32_t)__bfloat16_as_ushort(h3) << 16);
            lp.x = (uint32_t)__bfloat16_as_ushort(l0) | ((uint32_t)__bfloat16_as_ushort(l1) << 16);
            lp.y = (uint32_t)__bfloat16_as_ushort(l2) | ((uint32_t)__bfloat16_as_ushort(l3) << 16);
            *(uint2*)(sAH + r * WSTR + c4) = hp;
            *(uint2*)(sAL + r * WSTR + c4) = lp;
        }
        // stage weights: raw copy of pre-split padded images (34816 B each)
        {
            const uint4* src_h = (const uint4*)WH;
            const uint4* src_l = (const uint4*)WL;
            uint4* dst_h = (uint4*)sBH;
            uint4* dst_l = (uint4*)sBL;
            for (int t = tid; t < TILE * 2 / 16; t += 256) {   // 2176 chunks
                dst_h[t] = __ldg(src_h + t);
                dst_l[t] = __ldg(src_l + t);
            }
        }
        __syncthreads();

#pragma unroll
        for (int k0 = 0; k0 < DIM; k0 += 16) {
            uint32_t ah[4], al[4];
            ldmatrix_x4(ah, AH + aoff + k0 * 2);
            ldmatrix_x4(al, AL + aoff + k0 * 2);
#pragma unroll
            for (int n = 0; n < 16; ++n) {
                uint32_t bo = ((n * 8 + bl8) * WSTR + k0 + bk8) * 2;
                uint32_t bh[2], blo[2];
                ldmatrix_x2(bh,  BH + bo);
                ldmatrix_x2(blo, BL + bo);
                mma_bf16(d[n], ah, bh);
                mma_bf16(d[n], ah, blo);
                mma_bf16(d[n], al, bh);
            }
        }
    }

    // epilogue: fragment rows (lane>>2) and (lane>>2)+8; cols n*8 + (lane&3)*2
    const int r0g = row0 + wrow + (lane >> 2);
    const int r1g = r0g + 8;
    const int cb  = (lane & 3) * 2;
#pragma unroll
    for (int n = 0; n < 16; ++n) {
        int col = n * 8 + cb;
        float2 bb = *(const float2*)(bias + col);
        float v0 = d[n][0] + bb.x, v1 = d[n][1] + bb.y;
        float v2 = d[n][2] + bb.x, v3 = d[n][3] + bb.y;
        if (RELU) {
            v0 = fmaxf(v0, 0.f); v1 = fmaxf(v1, 0.f);
            v2 = fmaxf(v2, 0.f); v3 = fmaxf(v3, 0.f);
        }
        if (r0g < NN) *(float2*)(out + (size_t)r0g * DIM + col) = make_float2(v0, v1);
        if (r1g < NN) *(float2*)(out + (size_t)r1g * DIM + col) = make_float2(v2, v3);
    }
}

// ---------------------------------------------------------------------------
// kernel_launch — launch 3 = k_mma layer 1 (ncu target)
// inputs: t, x, edge_index, W1_l, W1_r, b1, W2_l, W2_r, b2, W3_l, W3_r, b3
// ---------------------------------------------------------------------------
extern "C" void kernel_launch(void* const* d_in, const int* in_sizes, int n_in,
                              void* d_out, int out_size) {
    const float* x   = (const float*)d_in[1];
    const int*   ei  = (const int*)d_in[2];
    const int*   src = ei;
    const int*   dst = ei + NE;
    const float* W1l = (const float*)d_in[3];
    const float* W1r = (const float*)d_in[4];
    const float* b1  = (const float*)d_in[5];
    const float* W2l = (const float*)d_in[6];
    const float* W2r = (const float*)d_in[7];
    const float* b2  = (const float*)d_in[8];
    const float* W3l = (const float*)d_in[9];
    const float* W3r = (const float*)d_in[10];
    const float* b3  = (const float*)d_in[11];
    float* out = (float*)d_out;

    float *mean, *h1, *h2;
    cudaGetSymbolAddress((void**)&mean, g_mean);
    cudaGetSymbolAddress((void**)&h1,  g_h1);
    cudaGetSymbolAddress((void**)&h2,  g_h2);
    __nv_bfloat16* wbf;
    cudaGetSymbolAddress((void**)&wbf, g_wbf);
    auto img = [&](int m, int hl) { return wbf + ((size_t)m * 2 + hl) * DIM * WSTR; };

    const int SMEM = 4 * DIM * WSTR * 2;   // 139264 B
    cudaFuncSetAttribute(k_mma<true>,  cudaFuncAttributeMaxDynamicSharedMemorySize, SMEM);
    cudaFuncSetAttribute(k_mma<false>, cudaFuncAttributeMaxDynamicSharedMemorySize, SMEM);

    const int AGG_BLOCKS = (NN * 32 + 255) / 256;

    // launches 0-1: prep (cursors + weight split), bucket
    k_prep<<<NB_INIT + 6, 256>>>(W1l, W1r, W2l, W2r, W3l, W3r);
    k_bucket<<<(NE + 255) / 256, 256>>>(src, dst);

    // layer 1 (launch 2 = agg, launch 3 = mma -> ncu)
    k_agg<<<AGG_BLOCKS, 256>>>(x, mean);
    k_mma<true><<<GRID_MMA, 256, SMEM>>>(mean, x, img(0,0), img(0,1), img(1,0), img(1,1), b1, h1);

    // layer 2
    k_agg<<<AGG_BLOCKS, 256>>>(h1, mean);
    k_mma<true><<<GRID_MMA, 256, SMEM>>>(mean, h1, img(2,0), img(2,1), img(3,0), img(3,1), b2, h2);

    // layer 3 (no relu)
    k_agg<<<AGG_BLOCKS, 256>>>(h2, mean);
    k_mma<false><<<GRID_MMA, 256, SMEM>>>(mean, h2, img(4,0), img(4,1), img(5,0), img(5,1), b3, out);
}

// round 12
// speedup vs baseline: 2.9067x; 1.1865x over previous
#include <cuda_runtime.h>
#include <cuda_bf16.h>
#include <cstdint>

#define NN 100000
#define NE 1600000
#define DIM 128
#define SLOTS 128
#define MT 128                    // M tile per block
#define WSTR 136                  // padded bf16 row stride (272B)
#define GRID_MMA ((NN + MT - 1) / MT)   // 782

typedef unsigned long long u64;

// ---------------------------------------------------------------------------
// Scratch (__device__ globals)
// ---------------------------------------------------------------------------
__device__ float g_mean[NN * DIM];
__device__ float g_h1[NN * DIM];
__device__ float g_h2[NN * DIM];
__device__ int   g_cursor[NN];
__device__ int   g_csrsrc[NN * SLOTS];
// pre-split transposed weights: [matrix 0..5][hi=0/lo=1][n*WSTR + k]
__device__ __nv_bfloat16 g_wbf[6][2][DIM * WSTR];

// ---------------------------------------------------------------------------
// helpers
// ---------------------------------------------------------------------------
__device__ __forceinline__ uint32_t smem_u32(const void* p) {
    uint32_t a;
    asm("{ .reg .u64 t; cvta.to.shared.u64 t, %1; cvt.u32.u64 %0, t; }" : "=r"(a) : "l"(p));
    return a;
}
__device__ __forceinline__ void ldmatrix_x4(uint32_t* r, uint32_t addr) {
    asm volatile("ldmatrix.sync.aligned.m8n8.x4.shared.b16 {%0,%1,%2,%3}, [%4];"
                 : "=r"(r[0]), "=r"(r[1]), "=r"(r[2]), "=r"(r[3]) : "r"(addr));
}
__device__ __forceinline__ void mma_bf16(float* d, const uint32_t* a, const uint32_t* b) {
    asm volatile(
        "mma.sync.aligned.m16n8k16.row.col.f32.bf16.bf16.f32 "
        "{%0,%1,%2,%3}, {%4,%5,%6,%7}, {%8,%9}, {%0,%1,%2,%3};"
        : "+f"(d[0]), "+f"(d[1]), "+f"(d[2]), "+f"(d[3])
        : "r"(a[0]), "r"(a[1]), "r"(a[2]), "r"(a[3]), "r"(b[0]), "r"(b[1]));
}

// ---------------------------------------------------------------------------
// prep: cursor init + 6 weight matrices -> transposed, split (hi/lo bf16)
// ---------------------------------------------------------------------------
#define NB_INIT ((NN + 255) / 256)

__global__ void k_prep(const float* W0, const float* W1, const float* W2,
                       const float* W3, const float* W4, const float* W5) {
    int b = blockIdx.x;
    if (b < NB_INIT) {
        int i = b * 256 + threadIdx.x;
        if (i < NN) g_cursor[i] = i * SLOTS;
        return;
    }
    int m = b - NB_INIT;
    const float* W = (m == 0) ? W0 : (m == 1) ? W1 : (m == 2) ? W2
                     : (m == 3) ? W3 : (m == 4) ? W4 : W5;
    __nv_bfloat16* wh = &g_wbf[m][0][0];
    __nv_bfloat16* wl = &g_wbf[m][1][0];
    for (int e = threadIdx.x; e < DIM * DIM; e += 256) {
        int n = e >> 7, k = e & 127;
        float v = __ldg(W + k * DIM + n);           // BT[n][k] = W[k][n]
        __nv_bfloat16 h = __float2bfloat16(v);
        __nv_bfloat16 l = __float2bfloat16(v - __bfloat162float(h));
        wh[n * WSTR + k] = h;
        wl[n * WSTR + k] = l;
    }
}

__global__ void k_bucket(const int* __restrict__ src, const int* __restrict__ dst) {
    int e = blockIdx.x * blockDim.x + threadIdx.x;
    if (e < NE) {
        int d = dst[e];
        int pos = atomicAdd(&g_cursor[d], 1);
        if (pos < d * SLOTS + SLOTS)
            g_csrsrc[pos] = src[e];
    }
}

// ---------------------------------------------------------------------------
// pull-mode mean aggregation: one warp per node.
// ---------------------------------------------------------------------------
__global__ void __launch_bounds__(256)
k_agg(const float* __restrict__ x, float* __restrict__ mean) {
    int node = (blockIdx.x * blockDim.x + threadIdx.x) >> 5;
    int lane = threadIdx.x & 31;
    if (node >= NN) return;
    int beg = node * SLOTS;
    int d   = min(__ldg(g_cursor + node) - beg, SLOTS);
    int end = beg + d;

    const float4* xv = (const float4*)x;
    float4 acc = make_float4(0.f, 0.f, 0.f, 0.f);
    for (int e = beg; e < end; e += 8) {
        int idx[8];
#pragma unroll
        for (int j = 0; j < 8; ++j)
            idx[j] = (e + j < end) ? __ldg(g_csrsrc + e + j) : -1;
#pragma unroll
        for (int j = 0; j < 8; ++j) {
            if (idx[j] >= 0) {
                float4 v = __ldg(xv + (size_t)idx[j] * 32 + lane);
                acc.x += v.x; acc.y += v.y; acc.z += v.z; acc.w += v.w;
            }
        }
    }
    float inv = (d > 0) ? (1.0f / (float)d) : 0.0f;
    acc.x *= inv; acc.y *= inv; acc.z *= inv; acc.w *= inv;
    ((float4*)(mean + (size_t)node * DIM))[lane] = acc;
}

// ---------------------------------------------------------------------------
// tensor-core SAGE GEMM (mma.sync bf16, split-precision), 512 threads:
//   out = act( mean @ Wl + hin @ Wr + b ),  A@W ~ AhWh + AhWl + AlWh
//
// 16 warps: warp w owns rows (w>>1)*16..+15, cols (w&1)*64..+63.
// d[8][4] (32 f32). B fragments loaded as ldmatrix.x4 covering an n-tile PAIR
// (two n8 tiles x both k-halves). SMEM layout identical to R11 (139 KB).
// ---------------------------------------------------------------------------
template <bool RELU>
__global__ void __launch_bounds__(512)
k_mma(const float* __restrict__ mean, const float* __restrict__ hin,
      const __nv_bfloat16* __restrict__ wl_h, const __nv_bfloat16* __restrict__ wl_l,
      const __nv_bfloat16* __restrict__ wr_h, const __nv_bfloat16* __restrict__ wr_l,
      const float* __restrict__ bias, float* __restrict__ out) {
    extern __shared__ __nv_bfloat16 sm[];
    constexpr int TILE = DIM * WSTR;              // 17408 bf16 = 34816 B
    __nv_bfloat16* sAH = sm;
    __nv_bfloat16* sAL = sm + TILE;
    __nv_bfloat16* sBH = sm + 2 * TILE;
    __nv_bfloat16* sBL = sm + 3 * TILE;
    const uint32_t base = smem_u32(sm);
    const uint32_t AH = base, AL = base + TILE * 2,
                   BH = base + 4 * TILE, BL = base + 6 * TILE;

    const int tid  = threadIdx.x;
    const int wid  = tid >> 5;
    const int lane = tid & 31;
    const int row0 = blockIdx.x * MT;
    const int wrow = (wid >> 1) * 16;     // warp's 16 rows
    const int ncol = (wid & 1) * 64;      // warp's 64-col half

    // A ldmatrix lane offset (bytes): rows wrow + (lane>>3&1)*8 + lane&7,
    // k-offset (lane>>4)*8
    const uint32_t aoff = ((wrow + ((lane >> 3) & 1) * 8 + (lane & 7)) * WSTR
                           + ((lane >> 4) * 8)) * 2;
    // B x4 lane offset: g=lane>>3: n += (g>>1)*8, k += (g&1)*8
    const uint32_t brow = (uint32_t)(ncol + ((lane >> 4) & 1) * 8 + (lane & 7));
    const uint32_t bkof = (uint32_t)(((lane >> 3) & 1) * 8);

    float d[8][4];
#pragma unroll
    for (int n = 0; n < 8; ++n)
#pragma unroll
        for (int j = 0; j < 4; ++j) d[n][j] = 0.f;

#pragma unroll
    for (int phase = 0; phase < 2; ++phase) {
        const float* A = phase ? hin : mean;
        const __nv_bfloat16* WH = phase ? wr_h : wl_h;
        const __nv_bfloat16* WL = phase ? wr_l : wl_l;

        __syncthreads();
        // stage A: split f32 -> hi/lo bf16 (4096 float4 over 512 threads)
        for (int t = tid; t < MT * 32; t += 512) {
            int r  = t >> 5;
            int c4 = (t & 31) * 4;
            int grow = row0 + r;
            float4 v = make_float4(0.f, 0.f, 0.f, 0.f);
            if (grow < NN)
                v = __ldg((const float4*)(A + (size_t)grow * DIM) + (t & 31));
            __nv_bfloat16 h0 = __float2bfloat16(v.x), h1 = __float2bfloat16(v.y),
                          h2 = __float2bfloat16(v.z), h3 = __float2bfloat16(v.w);
            __nv_bfloat16 l0 = __float2bfloat16(v.x - __bfloat162float(h0));
            __nv_bfloat16 l1 = __float2bfloat16(v.y - __bfloat162float(h1));
            __nv_bfloat16 l2 = __float2bfloat16(v.z - __bfloat162float(h2));
            __nv_bfloat16 l3 = __float2bfloat16(v.w - __bfloat162float(h3));
            uint2 hp, lp;
            hp.x = (uint32_t)__bfloat16_as_ushort(h0) | ((uint32_t)__bfloat16_as_ushort(h1) << 16);
            hp.y = (uint32_t)__bfloat16_as_ushort(h2) | ((uint32_t)__bfloat16_as_ushort(h3) << 16);
            lp.x = (uint32_t)__bfloat16_as_ushort(l0) | ((uint32_t)__bfloat16_as_ushort(l1) << 16);
            lp.y = (uint32_t)__bfloat16_as_ushort(l2) | ((uint32_t)__bfloat16_as_ushort(l3) << 16);
            *(uint2*)(sAH + r * WSTR + c4) = hp;
            *(uint2*)(sAL + r * WSTR + c4) = lp;
        }
        // stage weights: raw copy of pre-split padded images
        {
            const uint4* src_h = (const uint4*)WH;
            const uint4* src_l = (const uint4*)WL;
            uint4* dst_h = (uint4*)sBH;
            uint4* dst_l = (uint4*)sBL;
            for (int t = tid; t < TILE * 2 / 16; t += 512) {
                dst_h[t] = __ldg(src_h + t);
                dst_l[t] = __ldg(src_l + t);
            }
        }
        __syncthreads();

#pragma unroll
        for (int k0 = 0; k0 < DIM; k0 += 16) {
            uint32_t ah[4], al[4];
            ldmatrix_x4(ah, AH + aoff + k0 * 2);
            ldmatrix_x4(al, AL + aoff + k0 * 2);
#pragma unroll
            for (int np = 0; np < 4; ++np) {       // n-tile pairs
                uint32_t bo = ((brow + np * 16) * WSTR + k0 + bkof) * 2;
                uint32_t bh[4], bl[4];
                ldmatrix_x4(bh, BH + bo);
                ldmatrix_x4(bl, BL + bo);
                mma_bf16(d[np * 2],     ah, bh);
                mma_bf16(d[np * 2],     ah, bl);
                mma_bf16(d[np * 2],     al, bh);
                mma_bf16(d[np * 2 + 1], ah, bh + 2);
                mma_bf16(d[np * 2 + 1], ah, bl + 2);
                mma_bf16(d[np * 2 + 1], al, bh + 2);
            }
        }
    }

    // epilogue: rows wrow + lane>>2 (+8), cols ncol + n*8 + (lane&3)*2
    const int r0g = row0 + wrow + (lane >> 2);
    const int r1g = r0g + 8;
    const int cb  = (lane & 3) * 2;
#pragma unroll
    for (int n = 0; n < 8; ++n) {
        int col = ncol + n * 8 + cb;
        float2 bb = *(const float2*)(bias + col);
        float v0 = d[n][0] + bb.x, v1 = d[n][1] + bb.y;
        float v2 = d[n][2] + bb.x, v3 = d[n][3] + bb.y;
        if (RELU) {
            v0 = fmaxf(v0, 0.f); v1 = fmaxf(v1, 0.f);
            v2 = fmaxf(v2, 0.f); v3 = fmaxf(v3, 0.f);
        }
        if (r0g < NN) *(float2*)(out + (size_t)r0g * DIM + col) = make_float2(v0, v1);
        if (r1g < NN) *(float2*)(out + (size_t)r1g * DIM + col) = make_float2(v2, v3);
    }
}

// ---------------------------------------------------------------------------
// kernel_launch — launch 3 = k_mma layer 1 (ncu target)
// inputs: t, x, edge_index, W1_l, W1_r, b1, W2_l, W2_r, b2, W3_l, W3_r, b3
// ---------------------------------------------------------------------------
extern "C" void kernel_launch(void* const* d_in, const int* in_sizes, int n_in,
                              void* d_out, int out_size) {
    const float* x   = (const float*)d_in[1];
    const int*   ei  = (const int*)d_in[2];
    const int*   src = ei;
    const int*   dst = ei + NE;
    const float* W1l = (const float*)d_in[3];
    const float* W1r = (const float*)d_in[4];
    const float* b1  = (const float*)d_in[5];
    const float* W2l = (const float*)d_in[6];
    const float* W2r = (const float*)d_in[7];
    const float* b2  = (const float*)d_in[8];
    const float* W3l = (const float*)d_in[9];
    const float* W3r = (const float*)d_in[10];
    const float* b3  = (const float*)d_in[11];
    float* out = (float*)d_out;

    float *mean, *h1, *h2;
    cudaGetSymbolAddress((void**)&mean, g_mean);
    cudaGetSymbolAddress((void**)&h1,  g_h1);
    cudaGetSymbolAddress((void**)&h2,  g_h2);
    __nv_bfloat16* wbf;
    cudaGetSymbolAddress((void**)&wbf, g_wbf);
    auto img = [&](int m, int hl) { return wbf + ((size_t)m * 2 + hl) * DIM * WSTR; };

    const int SMEM = 4 * DIM * WSTR * 2;   // 139264 B
    cudaFuncSetAttribute(k_mma<true>,  cudaFuncAttributeMaxDynamicSharedMemorySize, SMEM);
    cudaFuncSetAttribute(k_mma<false>, cudaFuncAttributeMaxDynamicSharedMemorySize, SMEM);

    const int AGG_BLOCKS = (NN * 32 + 255) / 256;

    // launches 0-1: prep (cursors + weight split), bucket
    k_prep<<<NB_INIT + 6, 256>>>(W1l, W1r, W2l, W2r, W3l, W3r);
    k_bucket<<<(NE + 255) / 256, 256>>>(src, dst);

    // layer 1 (launch 2 = agg, launch 3 = mma -> ncu)
    k_agg<<<AGG_BLOCKS, 256>>>(x, mean);
    k_mma<true><<<GRID_MMA, 512, SMEM>>>(mean, x, img(0,0), img(0,1), img(1,0), img(1,1), b1, h1);

    // layer 2
    k_agg<<<AGG_BLOCKS, 256>>>(h1, mean);
    k_mma<true><<<GRID_MMA, 512, SMEM>>>(mean, h1, img(2,0), img(2,1), img(3,0), img(3,1), b2, h2);

    // layer 3 (no relu)
    k_agg<<<AGG_BLOCKS, 256>>>(h2, mean);
    k_mma<false><<<GRID_MMA, 512, SMEM>>>(mean, h2, img(4,0), img(4,1), img(5,0), img(5,1), b3, out);
}

// round 13
// speedup vs baseline: 3.0074x; 1.0346x over previous
#include <cuda_runtime.h>
#include <cuda_bf16.h>
#include <cstdint>

#define NN 100000
#define NE 1600000
#define DIM 128
#define SLOTS 128
#define MT 128                    // M tile per block
#define WSTR 136                  // padded bf16 row stride (272B)
#define GRID_MMA ((NN + MT - 1) / MT)   // 782

typedef unsigned long long u64;

// ---------------------------------------------------------------------------
// Scratch (__device__ globals)
// ---------------------------------------------------------------------------
__device__ float g_mean[NN * DIM];
__device__ float g_h1[NN * DIM];
__device__ float g_h2[NN * DIM];
__device__ int   g_cursor[NN];
__device__ int   g_csrsrc[NN * SLOTS];
// pre-split transposed weights: [matrix 0..5][hi=0/lo=1][n*WSTR + k]
__device__ __nv_bfloat16 g_wbf[6][2][DIM * WSTR];

// ---------------------------------------------------------------------------
// helpers
// ---------------------------------------------------------------------------
__device__ __forceinline__ uint32_t smem_u32(const void* p) {
    uint32_t a;
    asm("{ .reg .u64 t; cvta.to.shared.u64 t, %1; cvt.u32.u64 %0, t; }" : "=r"(a) : "l"(p));
    return a;
}
__device__ __forceinline__ void ldmatrix_x4(uint32_t* r, uint32_t addr) {
    asm volatile("ldmatrix.sync.aligned.m8n8.x4.shared.b16 {%0,%1,%2,%3}, [%4];"
                 : "=r"(r[0]), "=r"(r[1]), "=r"(r[2]), "=r"(r[3]) : "r"(addr));
}
__device__ __forceinline__ void mma_bf16(float* d, const uint32_t* a, const uint32_t* b) {
    asm volatile(
        "mma.sync.aligned.m16n8k16.row.col.f32.bf16.bf16.f32 "
        "{%0,%1,%2,%3}, {%4,%5,%6,%7}, {%8,%9}, {%0,%1,%2,%3};"
        : "+f"(d[0]), "+f"(d[1]), "+f"(d[2]), "+f"(d[3])
        : "r"(a[0]), "r"(a[1]), "r"(a[2]), "r"(a[3]), "r"(b[0]), "r"(b[1]));
}

// ---------------------------------------------------------------------------
// prep: cursor init + 6 weight matrices -> transposed, split (hi/lo bf16)
// ---------------------------------------------------------------------------
#define NB_INIT ((NN + 255) / 256)

__global__ void k_prep(const float* W0, const float* W1, const float* W2,
                       const float* W3, const float* W4, const float* W5) {
    int b = blockIdx.x;
    if (b < NB_INIT) {
        int i = b * 256 + threadIdx.x;
        if (i < NN) g_cursor[i] = i * SLOTS;
        return;
    }
    int m = b - NB_INIT;
    const float* W = (m == 0) ? W0 : (m == 1) ? W1 : (m == 2) ? W2
                     : (m == 3) ? W3 : (m == 4) ? W4 : W5;
    __nv_bfloat16* wh = &g_wbf[m][0][0];
    __nv_bfloat16* wl = &g_wbf[m][1][0];
    for (int e = threadIdx.x; e < DIM * DIM; e += 256) {
        int n = e >> 7, k = e & 127;
        float v = __ldg(W + k * DIM + n);           // BT[n][k] = W[k][n]
        __nv_bfloat16 h = __float2bfloat16(v);
        __nv_bfloat16 l = __float2bfloat16(v - __bfloat162float(h));
        wh[n * WSTR + k] = h;
        wl[n * WSTR + k] = l;
    }
}

__global__ void k_bucket(const int* __restrict__ src, const int* __restrict__ dst) {
    int e = blockIdx.x * blockDim.x + threadIdx.x;
    if (e < NE) {
        int d = dst[e];
        int pos = atomicAdd(&g_cursor[d], 1);
        if (pos < d * SLOTS + SLOTS)
            g_csrsrc[pos] = src[e];
    }
}

// ---------------------------------------------------------------------------
// pull-mode mean aggregation: one warp per node.
// ---------------------------------------------------------------------------
__global__ void __launch_bounds__(256)
k_agg(const float* __restrict__ x, float* __restrict__ mean) {
    int node = (blockIdx.x * blockDim.x + threadIdx.x) >> 5;
    int lane = threadIdx.x & 31;
    if (node >= NN) return;
    int beg = node * SLOTS;
    int d   = min(__ldg(g_cursor + node) - beg, SLOTS);
    int end = beg + d;

    const float4* xv = (const float4*)x;
    float4 acc = make_float4(0.f, 0.f, 0.f, 0.f);
    for (int e = beg; e < end; e += 8) {
        int idx[8];
#pragma unroll
        for (int j = 0; j < 8; ++j)
            idx[j] = (e + j < end) ? __ldg(g_csrsrc + e + j) : -1;
#pragma unroll
        for (int j = 0; j < 8; ++j) {
            if (idx[j] >= 0) {
                float4 v = __ldg(xv + (size_t)idx[j] * 32 + lane);
                acc.x += v.x; acc.y += v.y; acc.z += v.z; acc.w += v.w;
            }
        }
    }
    float inv = (d > 0) ? (1.0f / (float)d) : 0.0f;
    acc.x *= inv; acc.y *= inv; acc.z *= inv; acc.w *= inv;
    ((float4*)(mean + (size_t)node * DIM))[lane] = acc;
}

// ---------------------------------------------------------------------------
// tensor-core SAGE GEMM (mma.sync bf16, split-precision), 1024 threads:
//   out = act( mean @ Wl + hin @ Wr + b ),  A@W ~ AhWh + AhWl + AlWh
//
// 32 warps = 32 warps/SM (R12 had 16): warp w owns rows (w>>2)*16..+15,
// cols (w&3)*32..+31. d[4][4] = 16 f32 acc regs. Per k0: 2 A-ldmatrix.x4 +
// 2 n-pairs x 2 B-ldmatrix.x4 + 12 MMAs. SMEM unchanged (139 KB, 1 blk/SM).
// ---------------------------------------------------------------------------
template <bool RELU>
__global__ void __launch_bounds__(1024)
k_mma(const float* __restrict__ mean, const float* __restrict__ hin,
      const __nv_bfloat16* __restrict__ wl_h, const __nv_bfloat16* __restrict__ wl_l,
      const __nv_bfloat16* __restrict__ wr_h, const __nv_bfloat16* __restrict__ wr_l,
      const float* __restrict__ bias, float* __restrict__ out) {
    extern __shared__ __nv_bfloat16 sm[];
    constexpr int TILE = DIM * WSTR;              // 17408 bf16 = 34816 B
    __nv_bfloat16* sAH = sm;
    __nv_bfloat16* sAL = sm + TILE;
    __nv_bfloat16* sBH = sm + 2 * TILE;
    __nv_bfloat16* sBL = sm + 3 * TILE;
    const uint32_t base = smem_u32(sm);
    const uint32_t AH = base, AL = base + TILE * 2,
                   BH = base + 4 * TILE, BL = base + 6 * TILE;

    const int tid  = threadIdx.x;
    const int wid  = tid >> 5;
    const int lane = tid & 31;
    const int row0 = blockIdx.x * MT;
    const int wrow = (wid >> 2) * 16;     // warp's 16 rows
    const int ncol = (wid & 3) * 32;      // warp's 32-col quarter

    const uint32_t aoff = ((wrow + ((lane >> 3) & 1) * 8 + (lane & 7)) * WSTR
                           + ((lane >> 4) * 8)) * 2;
    const uint32_t brow = (uint32_t)(ncol + ((lane >> 4) & 1) * 8 + (lane & 7));
    const uint32_t bkof = (uint32_t)(((lane >> 3) & 1) * 8);

    float d[4][4];
#pragma unroll
    for (int n = 0; n < 4; ++n)
#pragma unroll
        for (int j = 0; j < 4; ++j) d[n][j] = 0.f;

#pragma unroll
    for (int phase = 0; phase < 2; ++phase) {
        const float* A = phase ? hin : mean;
        const __nv_bfloat16* WH = phase ? wr_h : wl_h;
        const __nv_bfloat16* WL = phase ? wr_l : wl_l;

        __syncthreads();
        // stage A: split f32 -> hi/lo bf16 (4096 float4 over 1024 threads)
        for (int t = tid; t < MT * 32; t += 1024) {
            int r  = t >> 5;
            int c4 = (t & 31) * 4;
            int grow = row0 + r;
            float4 v = make_float4(0.f, 0.f, 0.f, 0.f);
            if (grow < NN)
                v = __ldg((const float4*)(A + (size_t)grow * DIM) + (t & 31));
            __nv_bfloat16 h0 = __float2bfloat16(v.x), h1 = __float2bfloat16(v.y),
                          h2 = __float2bfloat16(v.z), h3 = __float2bfloat16(v.w);
            __nv_bfloat16 l0 = __float2bfloat16(v.x - __bfloat162float(h0));
            __nv_bfloat16 l1 = __float2bfloat16(v.y - __bfloat162float(h1));
            __nv_bfloat16 l2 = __float2bfloat16(v.z - __bfloat162float(h2));
            __nv_bfloat16 l3 = __float2bfloat16(v.w - __bfloat162float(h3));
            uint2 hp, lp;
            hp.x = (uint32_t)__bfloat16_as_ushort(h0) | ((uint32_t)__bfloat16_as_ushort(h1) << 16);
            hp.y = (uint32_t)__bfloat16_as_ushort(h2) | ((uint32_t)__bfloat16_as_ushort(h3) << 16);
            lp.x = (uint32_t)__bfloat16_as_ushort(l0) | ((uint32_t)__bfloat16_as_ushort(l1) << 16);
            lp.y = (uint32_t)__bfloat16_as_ushort(l2) | ((uint32_t)__bfloat16_as_ushort(l3) << 16);
            *(uint2*)(sAH + r * WSTR + c4) = hp;
            *(uint2*)(sAL + r * WSTR + c4) = lp;
        }
        // stage weights: raw copy of pre-split padded images
        {
            const uint4* src_h = (const uint4*)WH;
            const uint4* src_l = (const uint4*)WL;
            uint4* dst_h = (uint4*)sBH;
            uint4* dst_l = (uint4*)sBL;
            for (int t = tid; t < TILE * 2 / 16; t += 1024) {
                dst_h[t] = __ldg(src_h + t);
                dst_l[t] = __ldg(src_l + t);
            }
        }
        __syncthreads();

#pragma unroll
        for (int k0 = 0; k0 < DIM; k0 += 16) {
            uint32_t ah[4], al[4];
            ldmatrix_x4(ah, AH + aoff + k0 * 2);
            ldmatrix_x4(al, AL + aoff + k0 * 2);
#pragma unroll
            for (int np = 0; np < 2; ++np) {       // n-tile pairs
                uint32_t bo = ((brow + np * 16) * WSTR + k0 + bkof) * 2;
                uint32_t bh[4], bl[4];
                ldmatrix_x4(bh, BH + bo);
                ldmatrix_x4(bl, BL + bo);
                mma_bf16(d[np * 2],     ah, bh);
                mma_bf16(d[np * 2],     ah, bl);
                mma_bf16(d[np * 2],     al, bh);
                mma_bf16(d[np * 2 + 1], ah, bh + 2);
                mma_bf16(d[np * 2 + 1], ah, bl + 2);
                mma_bf16(d[np * 2 + 1], al, bh + 2);
            }
        }
    }

    // epilogue: rows wrow + lane>>2 (+8), cols ncol + n*8 + (lane&3)*2
    const int r0g = row0 + wrow + (lane >> 2);
    const int r1g = r0g + 8;
    const int cb  = (lane & 3) * 2;
#pragma unroll
    for (int n = 0; n < 4; ++n) {
        int col = ncol + n * 8 + cb;
        float2 bb = *(const float2*)(bias + col);
        float v0 = d[n][0] + bb.x, v1 = d[n][1] + bb.y;
        float v2 = d[n][2] + bb.x, v3 = d[n][3] + bb.y;
        if (RELU) {
            v0 = fmaxf(v0, 0.f); v1 = fmaxf(v1, 0.f);
            v2 = fmaxf(v2, 0.f); v3 = fmaxf(v3, 0.f);
        }
        if (r0g < NN) *(float2*)(out + (size_t)r0g * DIM + col) = make_float2(v0, v1);
        if (r1g < NN) *(float2*)(out + (size_t)r1g * DIM + col) = make_float2(v2, v3);
    }
}

// ---------------------------------------------------------------------------
// kernel_launch — launch 3 = k_mma layer 1 (ncu target)
// inputs: t, x, edge_index, W1_l, W1_r, b1, W2_l, W2_r, b2, W3_l, W3_r, b3
// ---------------------------------------------------------------------------
extern "C" void kernel_launch(void* const* d_in, const int* in_sizes, int n_in,
                              void* d_out, int out_size) {
    const float* x   = (const float*)d_in[1];
    const int*   ei  = (const int*)d_in[2];
    const int*   src = ei;
    const int*   dst = ei + NE;
    const float* W1l = (const float*)d_in[3];
    const float* W1r = (const float*)d_in[4];
    const float* b1  = (const float*)d_in[5];
    const float* W2l = (const float*)d_in[6];
    const float* W2r = (const float*)d_in[7];
    const float* b2  = (const float*)d_in[8];
    const float* W3l = (const float*)d_in[9];
    const float* W3r = (const float*)d_in[10];
    const float* b3  = (const float*)d_in[11];
    float* out = (float*)d_out;

    float *mean, *h1, *h2;
    cudaGetSymbolAddress((void**)&mean, g_mean);
    cudaGetSymbolAddress((void**)&h1,  g_h1);
    cudaGetSymbolAddress((void**)&h2,  g_h2);
    __nv_bfloat16* wbf;
    cudaGetSymbolAddress((void**)&wbf, g_wbf);
    auto img = [&](int m, int hl) { return wbf + ((size_t)m * 2 + hl) * DIM * WSTR; };

    const int SMEM = 4 * DIM * WSTR * 2;   // 139264 B
    cudaFuncSetAttribute(k_mma<true>,  cudaFuncAttributeMaxDynamicSharedMemorySize, SMEM);
    cudaFuncSetAttribute(k_mma<false>, cudaFuncAttributeMaxDynamicSharedMemorySize, SMEM);

    const int AGG_BLOCKS = (NN * 32 + 255) / 256;

    // launches 0-1: prep (cursors + weight split), bucket
    k_prep<<<NB_INIT + 6, 256>>>(W1l, W1r, W2l, W2r, W3l, W3r);
    k_bucket<<<(NE + 255) / 256, 256>>>(src, dst);

    // layer 1 (launch 2 = agg, launch 3 = mma -> ncu)
    k_agg<<<AGG_BLOCKS, 256>>>(x, mean);
    k_mma<true><<<GRID_MMA, 1024, SMEM>>>(mean, x, img(0,0), img(0,1), img(1,0), img(1,1), b1, h1);

    // layer 2
    k_agg<<<AGG_BLOCKS, 256>>>(h1, mean);
    k_mma<true><<<GRID_MMA, 1024, SMEM>>>(mean, h1, img(2,0), img(2,1), img(3,0), img(3,1), b2, h2);

    // layer 3 (no relu)
    k_agg<<<AGG_BLOCKS, 256>>>(h2, mean);
    k_mma<false><<<GRID_MMA, 1024, SMEM>>>(mean, h2, img(4,0), img(4,1), img(5,0), img(5,1), b3, out);
}